// round 1
// baseline (speedup 1.0000x reference)
#include <cuda_runtime.h>
#include <cstdint>

// Problem constants (from reference: B=4, S=1024, K=32, V=32000)
#define BB 4
#define SS 1024
#define KK 32
#define VV 32000
static const int ROWS = BB * SS;  // 4096

// ---------------------------------------------------------------------------
// Kernel 1: zero-fill the output (524 MB). Pure write-bandwidth bound.
// ---------------------------------------------------------------------------
__global__ void zero_kernel(float4* __restrict__ out, int n4) {
    int i = blockIdx.x * blockDim.x + threadIdx.x;
    if (i < n4) out[i] = make_float4(0.f, 0.f, 0.f, 0.f);
}

// ---------------------------------------------------------------------------
// Kernel 2: one warp per (b,s) row. Computes probs[K=32] and scatters into
// the zeroed output via atomicAdd (duplicate tgt indices are possible).
//
// Only the live subgraph of the reference is computed:
//   label_counts -> fc2 -> tempe ;  lkf/lsp -> fc1 -> noise_logit
//   probs = softmax(-knn_dists * tempe + noise_logit)
// (top_k(network_probs), dfc_w, sim_lambda, knn_lambda are dead code.)
// ---------------------------------------------------------------------------
__global__ void __launch_bounds__(256) combiner_kernel(
    const int*   __restrict__ tgt,
    const float* __restrict__ dists,
    const float* __restrict__ kkf,
    const float* __restrict__ nsp,
    const float* __restrict__ fc1_w1,  // (2,4)
    const float* __restrict__ fc1_b1,  // (4)
    const float* __restrict__ fc1_w2,  // (4,1)
    const float* __restrict__ fc1_b2,  // (1)
    const float* __restrict__ fc2_w1,  // (64,32)
    const float* __restrict__ fc2_b1,  // (32)
    const float* __restrict__ fc2_w2,  // (32,2)
    const float* __restrict__ fc2_b2,  // (2)
    float*       __restrict__ out)     // (ROWS, VV), pre-zeroed
{
    const unsigned FULL = 0xffffffffu;
    int gwarp = (blockIdx.x * blockDim.x + threadIdx.x) >> 5;
    int lane  = threadIdx.x & 31;
    if (gwarp >= ROWS) return;

    int   base = gwarp * KK + lane;
    int   t    = tgt[base];
    float d    = dists[base];
    float lkf  = logf(kkf[base]);
    float lsp  = logf(nsp[base]);

    // --- label_counts: distinct nonzero labels in the prefix [0..lane] -----
    // first-occurrence flag for this lane's label
    int fo = (t != 0) ? 1 : 0;
    #pragma unroll
    for (int j = 0; j < 31; j++) {
        int tj = __shfl_sync(FULL, t, j);
        if (j < lane && tj == t) fo = 0;
    }
    // inclusive warp prefix sum of fo
    float lc = (float)fo;
    #pragma unroll
    for (int off = 1; off < 32; off <<= 1) {
        float v = __shfl_up_sync(FULL, lc, off);
        if (lane >= off) lc += v;
    }

    // --- fc1: noise_logit = tanh([lkf,lsp] @ W1 + b1) @ W2 + b2 ------------
    float noise = fc1_b2[0];
    #pragma unroll
    for (int m = 0; m < 4; m++) {
        float h = fmaf(lkf, fc1_w1[m], fmaf(lsp, fc1_w1[4 + m], fc1_b1[m]));
        noise = fmaf(tanhf(h), fc1_w2[m], noise);
    }

    // --- fc2: hidden[lane] = b1[lane] + sum_j feat[j] * W1[j][lane] --------
    // feat = [knn_dists(32), label_counts(32)]
    float hid = fc2_b1[lane];
    #pragma unroll
    for (int j = 0; j < 32; j++) {
        float fj = __shfl_sync(FULL, d, j);
        hid = fmaf(fj, fc2_w1[j * 32 + lane], hid);
    }
    #pragma unroll
    for (int j = 0; j < 32; j++) {
        float fj = __shfl_sync(FULL, lc, j);
        hid = fmaf(fj, fc2_w1[(32 + j) * 32 + lane], hid);
    }
    float ht = tanhf(hid);

    // lambda_logit[1] = sum_h tanh(hidden[h]) * W2[h][1]  (+ b2[1])
    float l1 = ht * fc2_w2[lane * 2 + 1];
    #pragma unroll
    for (int off = 16; off; off >>= 1) l1 += __shfl_xor_sync(FULL, l1, off);
    l1 += fc2_b2[1];
    float tempe = 1.f / (1.f + expf(-l1));

    // --- probs = softmax over K of (-d * tempe + noise) --------------------
    float logit = fmaf(-d, tempe, noise);
    float mx = logit;
    #pragma unroll
    for (int off = 16; off; off >>= 1) mx = fmaxf(mx, __shfl_xor_sync(FULL, mx, off));
    float e = expf(logit - mx);
    float s = e;
    #pragma unroll
    for (int off = 16; off; off >>= 1) s += __shfl_xor_sync(FULL, s, off);
    float p = e / s;

    // --- scatter-add into the vocab dim ------------------------------------
    atomicAdd(out + (size_t)gwarp * VV + t, p);
}

// ---------------------------------------------------------------------------
// metadata order:
//  0 tgt_index(i32) 1 knn_dists 2 knn_key_feature 3 network_probs(UNUSED)
//  4 network_select_probs 5 dfc_w(UNUSED) 6 dfc_b(UNUSED)
//  7 fc1_w1 8 fc1_b1 9 fc1_w2 10 fc1_b2 11 fc2_w1 12 fc2_b1 13 fc2_w2 14 fc2_b2
// ---------------------------------------------------------------------------
extern "C" void kernel_launch(void* const* d_in, const int* in_sizes, int n_in,
                              void* d_out, int out_size) {
    const int*   tgt    = (const int*)  d_in[0];
    const float* dists  = (const float*)d_in[1];
    const float* kkf    = (const float*)d_in[2];
    const float* nsp    = (const float*)d_in[4];
    const float* fc1_w1 = (const float*)d_in[7];
    const float* fc1_b1 = (const float*)d_in[8];
    const float* fc1_w2 = (const float*)d_in[9];
    const float* fc1_b2 = (const float*)d_in[10];
    const float* fc2_w1 = (const float*)d_in[11];
    const float* fc2_b1 = (const float*)d_in[12];
    const float* fc2_w2 = (const float*)d_in[13];
    const float* fc2_b2 = (const float*)d_in[14];
    float* out = (float*)d_out;

    int n4 = out_size / 4;  // 131072000 / 4 = 32768000 float4s
    zero_kernel<<<(n4 + 255) / 256, 256>>>((float4*)out, n4);

    int nwarps = ROWS;                 // one warp per row
    int threads = 256;                 // 8 warps/block
    int blocks = (nwarps * 32 + threads - 1) / threads;  // 512
    combiner_kernel<<<blocks, threads>>>(tgt, dists, kkf, nsp,
                                         fc1_w1, fc1_b1, fc1_w2, fc1_b2,
                                         fc2_w1, fc2_b1, fc2_w2, fc2_b2,
                                         out);
}